// round 13
// baseline (speedup 1.0000x reference)
#include <cuda_runtime.h>
#include <cstdint>

#define NIDS   1000000
#define ZCH    400000
#define DIM    128
#define TOTAL  (2 * NIDS)
#define HASHSZ 4000000

// Static scratch (no allocations allowed). Zero-initialized at module load.
// inv maps store slot+1; 0 means "unmatched" -> collision slot ZCH-1.
// Entries are rewritten identically by scatter_kernel on every launch.
__device__ double   g_acc;
__device__ unsigned g_done;
__device__ int      g_inv0[HASHSZ];
__device__ int      g_inv1[HASHSZ];

// Table values < 4M < 2^22: if the buffer is int64, the odd 32-bit words of
// the first entries are all 0; sorted random int32 data -> essentially never.
__device__ __forceinline__ bool sniff_is64(const unsigned* __restrict__ w) {
    return (w[1] | w[3] | w[5] | w[7]) == 0u;
}

// L2 evict_last policy (scalar form requires createpolicy + cache_hint on
// sm_103; the bare .L2::evict_last qualifier is vector-only). Keeps the
// reused-across-replays inv maps young in L2 while ~120MB/launch of
// streaming data evicts itself.
__device__ __forceinline__ uint64_t mk_evict_last_policy() {
    uint64_t pol;
    asm("createpolicy.fractional.L2::evict_last.b64 %0, 1.0;" : "=l"(pol));
    return pol;
}
__device__ __forceinline__ int ld_evict_last(const int* p, uint64_t pol) {
    int v;
    asm("ld.global.L2::cache_hint.b32 %0, [%1], %2;"
        : "=r"(v) : "l"(p), "l"(pol));
    return v;
}
__device__ __forceinline__ void st_evict_last(int* p, int v, uint64_t pol) {
    asm volatile("st.global.L2::cache_hint.b32 [%0], %1, %2;"
                 :: "l"(p), "r"(v), "l"(pol));
}

// ---------------------------------------------------------------------------
// 1) Scatter slot+1 into the inverse maps. lower_bound semantics: first
//    occurrence wins for duplicates (branch on sorted neighbor, no atomics).
// ---------------------------------------------------------------------------
__global__ __launch_bounds__(256) void scatter_kernel(
    const void* __restrict__ m0v, const void* __restrict__ m1v)
{
    const int tid = blockIdx.x * blockDim.x + threadIdx.x;
    if (tid >= 2 * ZCH) return;
    const int feat = (tid >= ZCH) ? 1 : 0;
    const int j    = feat ? (tid - ZCH) : tid;
    const void* mv = feat ? m1v : m0v;
    int* inv       = feat ? g_inv1 : g_inv0;

    const bool is64 = sniff_is64((const unsigned*)m0v);
    int id, prev = -1;
    if (is64) {
        const long long* m = (const long long*)mv;
        id = (int)m[j];
        if (j > 0) prev = (int)m[j - 1];
    } else {
        const int* m = (const int*)mv;
        id = m[j];
        if (j > 0) prev = m[j - 1];
    }
    if (j == 0 || prev != id)
        st_evict_last(inv + id, j + 1, mk_evict_last_policy());
}

// ---------------------------------------------------------------------------
// 2) Main: depth-2 modulo-scheduled pipeline (R7 structure). Per iteration:
//      - consume cell(n)   [inv load issued 1 full iteration ago]
//      - issue  inv(n+1)   [from id loaded 1 full iteration ago]
//      - issue  id(n+2)
//    Inv loads use the L2 evict_last policy (map stays L2-resident).
//    Hot-row contribution folded algebraically; last-block finalize.
// ---------------------------------------------------------------------------
__global__ __launch_bounds__(256) void sparse_arch_kernel(
    const void* __restrict__ ids0v, const void* __restrict__ ids1v,
    const void* __restrict__ m0v,
    const float* __restrict__ e0,   const float* __restrict__ e1,
    float* __restrict__ out)
{
    __shared__ double blk_acc;
    if (threadIdx.x == 0) blk_acc = 0.0;
    __syncthreads();

    const int  lane = threadIdx.x & 31;
    const int  wpb  = blockDim.x >> 5;
    const int  wg   = blockIdx.x * wpb + (threadIdx.x >> 5);
    const int  nw   = gridDim.x * wpb;
    const int  step = nw * 32;
    const bool is64 = sniff_is64((const unsigned*)m0v);
    const uint64_t pol = mk_evict_last_policy();

    // Streaming id load for chunk at 'b' (clamped to 0 when OOB; result
    // unused in that case). feat is warp-uniform because NIDS % 32 == 0.
    auto load_id = [&](int b, int& feat_o) -> int {
        const int bb  = (b < TOTAL) ? b : 0;
        const int idx = bb + lane;
        const int f   = (idx >= NIDS) ? 1 : 0;
        const int i   = idx - (f ? NIDS : 0);
        feat_o = f;
        if (is64)  // little-endian low word; values < 2^22
            return __ldcs((const int*)(f ? ids1v : ids0v) + (i << 1));
        else
            return __ldcs((const int*)(f ? ids1v : ids0v) + i);
    };

    // Collision-row sums (broadcast to all lanes), computed once per warp.
    const float4 h0 = ((const float4*)(e0 + (size_t)(ZCH - 1) * DIM))[lane];
    const float4 h1 = ((const float4*)(e1 + (size_t)(ZCH - 1) * DIM))[lane];
    float hs0 = (h0.x + h0.y) + (h0.z + h0.w);
    float hs1 = (h1.x + h1.y) + (h1.z + h1.w);
    #pragma unroll
    for (int o = 16; o > 0; o >>= 1) {
        hs0 += __shfl_xor_sync(0xffffffffu, hs0, o);
        hs1 += __shfl_xor_sync(0xffffffffu, hs1, o);
    }

    float     s    = 0.0f;
    long long hot0 = 0, hot1 = 0;

    // Prologue (every warp has >= 1 chunk: step = 303104 < TOTAL).
    int featA, cellA;          // chunk n:   inv result pending
    int featB, idB;            // chunk n+1: id loaded, inv not yet issued
    {
        int idA = load_id(wg * 32, featA);
        cellA = ld_evict_last((featA ? g_inv1 : g_inv0) + idA, pol);
        idB   = load_id(wg * 32 + step, featB);
    }

    for (int base = wg * 32; base < TOTAL; base += step) {
        // Issue inv(n+1) from the already-loaded idB.
        int cellB = 0;
        if (base + step < TOTAL)
            cellB = ld_evict_last((featB ? g_inv1 : g_inv0) + idB, pol);

        // Issue id(n+2).
        int featC;
        const int idC = load_id(base + 2 * step, featC);

        // ---- Process chunk n (cellA has had a full iteration in flight) ----
        const int slot = cellA ? (cellA - 1) : (ZCH - 1);
        out[1 + base + lane] = (float)slot;   // default policy: lets L2 merge
                                              // the misaligned partial sectors

        const unsigned hotm = __ballot_sync(0xffffffffu, slot == ZCH - 1);
        if (featA) hot1 += __popc(hotm); else hot0 += __popc(hotm);

        // Cold-row gathers (~3 of 32), prefetch-depth-2 so loads overlap.
        unsigned nh = ~hotm;
        if (nh) {
            const float* e = featA ? e1 : e0;
            int j = __ffs(nh) - 1; nh &= nh - 1;
            int sl = __shfl_sync(0xffffffffu, slot, j);
            float4 v = __ldcs((const float4*)(e + (size_t)sl * DIM) + lane);
            while (nh) {
                j = __ffs(nh) - 1; nh &= nh - 1;
                sl = __shfl_sync(0xffffffffu, slot, j);
                const float4 v2 =
                    __ldcs((const float4*)(e + (size_t)sl * DIM) + lane);
                s += (v.x + v.y) + (v.z + v.w);
                v = v2;
            }
            s += (v.x + v.y) + (v.z + v.w);
        }

        // Rotate pipeline stages.
        featA = featB; cellA = cellB;
        featB = featC; idB   = idC;
    }

    #pragma unroll
    for (int o = 16; o > 0; o >>= 1)
        s += __shfl_down_sync(0xffffffffu, s, o);

    if (lane == 0) {
        const double t = (double)s
                       + (double)hot0 * (double)hs0
                       + (double)hot1 * (double)hs1;
        atomicAdd(&blk_acc, t);
    }
    __syncthreads();

    if (threadIdx.x == 0) {
        atomicAdd(&g_acc, blk_acc);
        __threadfence();
        const unsigned done = atomicAdd(&g_done, 1u);
        if (done == gridDim.x - 1) {              // last block finalizes
            const double total = atomicAdd(&g_acc, 0.0);
            out[0] = (float)(total / ((double)TOTAL * (double)DIM));
            g_acc  = 0.0;                          // reset for next replay
            g_done = 0u;
        }
    }
}

// ---------------------------------------------------------------------------
// Launch: 2 kernels, graph-capturable, allocation-free.
// Inputs (metadata order): ids_0, ids_1, mch_ids_0, mch_ids_1, emb_0, emb_1
// Output: [loss, remapped_0 (1M), remapped_1 (1M)] as float32.
// ---------------------------------------------------------------------------
extern "C" void kernel_launch(void* const* d_in, const int* in_sizes, int n_in,
                              void* d_out, int out_size)
{
    const void*  ids0 = d_in[0];
    const void*  ids1 = d_in[1];
    const void*  m0   = d_in[2];
    const void*  m1   = d_in[3];
    const float* e0   = (const float*)d_in[4];
    const float* e1   = (const float*)d_in[5];
    float* out = (float*)d_out;

    const int threads = 256;
    scatter_kernel<<<(2 * ZCH + threads - 1) / threads, threads>>>(m0, m1);
    sparse_arch_kernel<<<148 * 8, threads>>>(ids0, ids1, m0, e0, e1, out);
}

// round 14
// speedup vs baseline: 1.2182x; 1.2182x over previous
#include <cuda_runtime.h>
#include <cstdint>

#define NIDS   1000000
#define ZCH    400000
#define DIM    128
#define TOTAL  (2 * NIDS)
#define HASHSZ 4000000

// Static scratch (no allocations allowed). Zero-initialized at module load.
// inv maps store slot+1; 0 means "unmatched" -> collision slot ZCH-1.
// Entries are rewritten identically by scatter_kernel on every launch.
__device__ double   g_acc;
__device__ unsigned g_done;
__device__ int      g_inv0[HASHSZ];
__device__ int      g_inv1[HASHSZ];

// Table values < 4M < 2^22: if the buffer is int64, the odd 32-bit words of
// the first entries are all 0; sorted random int32 data -> essentially never.
__device__ __forceinline__ bool sniff_is64(const unsigned* __restrict__ w) {
    return (w[1] | w[3] | w[5] | w[7]) == 0u;
}

// ---------------------------------------------------------------------------
// 1) Scatter slot+1 into the inverse maps. lower_bound semantics: first
//    occurrence wins for duplicates (branch on sorted neighbor, no atomics).
// ---------------------------------------------------------------------------
__global__ __launch_bounds__(256) void scatter_kernel(
    const void* __restrict__ m0v, const void* __restrict__ m1v)
{
    const int tid = blockIdx.x * blockDim.x + threadIdx.x;
    if (tid >= 2 * ZCH) return;
    const int feat = (tid >= ZCH) ? 1 : 0;
    const int j    = feat ? (tid - ZCH) : tid;
    const void* mv = feat ? m1v : m0v;
    int* inv       = feat ? g_inv1 : g_inv0;

    const bool is64 = sniff_is64((const unsigned*)m0v);
    int id, prev = -1;
    if (is64) {
        const long long* m = (const long long*)mv;
        id = (int)m[j];
        if (j > 0) prev = (int)m[j - 1];
    } else {
        const int* m = (const int*)mv;
        id = m[j];
        if (j > 0) prev = m[j - 1];
    }
    if (j == 0 || prev != id) inv[id] = j + 1;
}

// ---------------------------------------------------------------------------
// 2) Main: depth-2 modulo-scheduled pipeline (converged R7 structure).
//    Per iteration:
//      - consume cell(n)   [inv load issued 1 full iteration ago]
//      - issue  inv(n+1)   [from id loaded 1 full iteration ago]
//      - issue  id(n+2)
//    Inv loads bypass L1 (__ldcg): random over 32MB, ~0% L1 hit.
//    Hot-row contribution folded algebraically; last-block finalize.
// ---------------------------------------------------------------------------
__global__ __launch_bounds__(256) void sparse_arch_kernel(
    const void* __restrict__ ids0v, const void* __restrict__ ids1v,
    const void* __restrict__ m0v,
    const float* __restrict__ e0,   const float* __restrict__ e1,
    float* __restrict__ out)
{
    __shared__ double blk_acc;
    if (threadIdx.x == 0) blk_acc = 0.0;
    __syncthreads();

    const int  lane = threadIdx.x & 31;
    const int  wpb  = blockDim.x >> 5;
    const int  wg   = blockIdx.x * wpb + (threadIdx.x >> 5);
    const int  nw   = gridDim.x * wpb;
    const int  step = nw * 32;
    const bool is64 = sniff_is64((const unsigned*)m0v);

    // Streaming id load for chunk at 'b' (clamped to 0 when OOB; result
    // unused in that case). feat is warp-uniform because NIDS % 32 == 0.
    auto load_id = [&](int b, int& feat_o) -> int {
        const int bb  = (b < TOTAL) ? b : 0;
        const int idx = bb + lane;
        const int f   = (idx >= NIDS) ? 1 : 0;
        const int i   = idx - (f ? NIDS : 0);
        feat_o = f;
        if (is64)  // little-endian low word; values < 2^22
            return __ldcs((const int*)(f ? ids1v : ids0v) + (i << 1));
        else
            return __ldcs((const int*)(f ? ids1v : ids0v) + i);
    };

    // Collision-row sums (broadcast to all lanes), computed once per warp.
    const float4 h0 = ((const float4*)(e0 + (size_t)(ZCH - 1) * DIM))[lane];
    const float4 h1 = ((const float4*)(e1 + (size_t)(ZCH - 1) * DIM))[lane];
    float hs0 = (h0.x + h0.y) + (h0.z + h0.w);
    float hs1 = (h1.x + h1.y) + (h1.z + h1.w);
    #pragma unroll
    for (int o = 16; o > 0; o >>= 1) {
        hs0 += __shfl_xor_sync(0xffffffffu, hs0, o);
        hs1 += __shfl_xor_sync(0xffffffffu, hs1, o);
    }

    float s    = 0.0f;
    int   hot0 = 0, hot1 = 0;      // per-warp counts <= ~212: int is enough

    // Prologue (every warp has >= 1 chunk: step = 303104 < TOTAL).
    int featA, cellA;          // chunk n:   inv result pending
    int featB, idB;            // chunk n+1: id loaded, inv not yet issued
    {
        int idA = load_id(wg * 32, featA);
        cellA = __ldcg((featA ? g_inv1 : g_inv0) + idA);
        idB   = load_id(wg * 32 + step, featB);
    }

    for (int base = wg * 32; base < TOTAL; base += step) {
        // Issue inv(n+1) from the already-loaded idB.
        int cellB = 0;
        if (base + step < TOTAL)
            cellB = __ldcg((featB ? g_inv1 : g_inv0) + idB);

        // Issue id(n+2).
        int featC;
        const int idC = load_id(base + 2 * step, featC);

        // ---- Process chunk n (cellA has had a full iteration in flight) ----
        const int slot = cellA ? (cellA - 1) : (ZCH - 1);
        __stcs(out + 1 + base + lane, (float)slot);

        const unsigned hotm = __ballot_sync(0xffffffffu, slot == ZCH - 1);
        if (featA) hot1 += __popc(hotm); else hot0 += __popc(hotm);

        // Cold-row gathers (~3 of 32), prefetch-depth-2 so loads overlap.
        unsigned nh = ~hotm;
        if (nh) {
            const float* e = featA ? e1 : e0;
            int j = __ffs(nh) - 1; nh &= nh - 1;
            int sl = __shfl_sync(0xffffffffu, slot, j);
            float4 v = __ldcs((const float4*)(e + (size_t)sl * DIM) + lane);
            while (nh) {
                j = __ffs(nh) - 1; nh &= nh - 1;
                sl = __shfl_sync(0xffffffffu, slot, j);
                const float4 v2 =
                    __ldcs((const float4*)(e + (size_t)sl * DIM) + lane);
                s += (v.x + v.y) + (v.z + v.w);
                v = v2;
            }
            s += (v.x + v.y) + (v.z + v.w);
        }

        // Rotate pipeline stages.
        featA = featB; cellA = cellB;
        featB = featC; idB   = idC;
    }

    #pragma unroll
    for (int o = 16; o > 0; o >>= 1)
        s += __shfl_down_sync(0xffffffffu, s, o);

    if (lane == 0) {
        const double t = (double)s
                       + (double)hot0 * (double)hs0
                       + (double)hot1 * (double)hs1;
        atomicAdd(&blk_acc, t);
    }
    __syncthreads();

    if (threadIdx.x == 0) {
        atomicAdd(&g_acc, blk_acc);
        __threadfence();
        const unsigned done = atomicAdd(&g_done, 1u);
        if (done == gridDim.x - 1) {              // last block finalizes
            const double total = atomicAdd(&g_acc, 0.0);
            out[0] = (float)(total / ((double)TOTAL * (double)DIM));
            g_acc  = 0.0;                          // reset for next replay
            g_done = 0u;
        }
    }
}

// ---------------------------------------------------------------------------
// Launch: 2 kernels, graph-capturable, allocation-free.
// Inputs (metadata order): ids_0, ids_1, mch_ids_0, mch_ids_1, emb_0, emb_1
// Output: [loss, remapped_0 (1M), remapped_1 (1M)] as float32.
// ---------------------------------------------------------------------------
extern "C" void kernel_launch(void* const* d_in, const int* in_sizes, int n_in,
                              void* d_out, int out_size)
{
    const void*  ids0 = d_in[0];
    const void*  ids1 = d_in[1];
    const void*  m0   = d_in[2];
    const void*  m1   = d_in[3];
    const float* e0   = (const float*)d_in[4];
    const float* e1   = (const float*)d_in[5];
    float* out = (float*)d_out;

    const int threads = 256;
    scatter_kernel<<<(2 * ZCH + threads - 1) / threads, threads>>>(m0, m1);
    sparse_arch_kernel<<<148 * 8, threads>>>(ids0, ids1, m0, e0, e1, out);
}